// round 10
// baseline (speedup 1.0000x reference)
#include <cuda_runtime.h>
#include <cuda_bf16.h>

#define N 8192
#define MARGIN 0.2f
#define INV_LAMB 83.333336f   // 1 / 0.012

#define BLOCKS 512
#define RPB 16                // rows per block: 512 * 16 = 8192
#define THREADS 512
#define CPT 16                // columns per thread: 512 * 16 = 8192
#define NU4 1024              // uint4 (8 bf16) per row
#define NF4 2048              // float4 per row
#define PGROUPS 16            // 512 partial rows -> 16 groups of 32

// ---- scratch (static __device__ globals; no allocations) ----
__device__ uint4  g_K4[(size_t)N * N / 8];        // K in bf16 (128 MB)
__device__ float  g_r[N];
__device__ float  g_c[N];
__device__ float  g_d[N];
__device__ float  g_partial[(size_t)BLOCKS * N];  // col partials (16 MB)
__device__ float  g_partial2[(size_t)PGROUPS * N];// stage-2 partials (512 KB)
__device__ float  g_block_loss[BLOCKS];

__device__ __forceinline__ float warp_sum(float v) {
    v += __shfl_xor_sync(0xffffffffu, v, 16);
    v += __shfl_xor_sync(0xffffffffu, v, 8);
    v += __shfl_xor_sync(0xffffffffu, v, 4);
    v += __shfl_xor_sync(0xffffffffu, v, 2);
    v += __shfl_xor_sync(0xffffffffu, v, 1);
    return v;
}

// reduce the 16 per-warp sums (written by warp leaders) using one warp-wide
// shuffle tree; every thread gets the total.  Caller must __syncthreads first.
__device__ __forceinline__ float tail_sum16(const float* red16, int lane) {
    float v = (lane < 16) ? red16[lane] : 0.f;
    v += __shfl_xor_sync(0xffffffffu, v, 8);
    v += __shfl_xor_sync(0xffffffffu, v, 4);
    v += __shfl_xor_sync(0xffffffffu, v, 2);
    v += __shfl_xor_sync(0xffffffffu, v, 1);
    return __shfl_sync(0xffffffffu, v, 0);
}

__device__ __forceinline__ float2 unpack_bf2(unsigned u) {
    float2 f;
    f.x = __uint_as_float(u << 16);
    f.y = __uint_as_float(u & 0xffff0000u);
    return f;
}

__device__ __forceinline__ unsigned pack_bf2(float lo, float hi) {
    __nv_bfloat162 h = __floats2bfloat162_rn(lo, hi);
    return *reinterpret_cast<unsigned*>(&h);
}

__device__ __forceinline__ void unpack16(const uint4& a, const uint4& b, float* k) {
    float2 p;
    p = unpack_bf2(a.x); k[0] = p.x;  k[1] = p.y;
    p = unpack_bf2(a.y); k[2] = p.x;  k[3] = p.y;
    p = unpack_bf2(a.z); k[4] = p.x;  k[5] = p.y;
    p = unpack_bf2(a.w); k[6] = p.x;  k[7] = p.y;
    p = unpack_bf2(b.x); k[8] = p.x;  k[9] = p.y;
    p = unpack_bf2(b.y); k[10] = p.x; k[11] = p.y;
    p = unpack_bf2(b.z); k[12] = p.x; k[13] = p.y;
    p = unpack_bf2(b.w); k[14] = p.x; k[15] = p.y;
}

// ============================================================================
// pass1_fused: K = exp((s-1)/lamb) -> bf16 cache; row update with c == 1;
// col partials with new r.  512 CTAs x 16 rows.
// ============================================================================
__global__ __launch_bounds__(THREADS, 2) void pass1_fused(const float* __restrict__ sims) {
    int t = threadIdx.x;
    int wid = t >> 5, lane = t & 31;
    int row0 = blockIdx.x * RPB;
    __shared__ float red[2][16];

    const float4* __restrict__ sbase = (const float4*)sims + (size_t)row0 * NF4 + t * 4;
    uint4* __restrict__ kbase = g_K4 + (size_t)row0 * NU4 + t * 2;

    float acc[CPT];
    #pragma unroll
    for (int i = 0; i < CPT; i++) acc[i] = 0.f;

    for (int r = 0; r < RPB; r++) {
        const float4* sp = sbase + (size_t)r * NF4;
        float4 s0 = sp[0], s1 = sp[1], s2 = sp[2], s3 = sp[3];
        float k[CPT];
        k[0]  = __expf((s0.x - 1.0f) * INV_LAMB);
        k[1]  = __expf((s0.y - 1.0f) * INV_LAMB);
        k[2]  = __expf((s0.z - 1.0f) * INV_LAMB);
        k[3]  = __expf((s0.w - 1.0f) * INV_LAMB);
        k[4]  = __expf((s1.x - 1.0f) * INV_LAMB);
        k[5]  = __expf((s1.y - 1.0f) * INV_LAMB);
        k[6]  = __expf((s1.z - 1.0f) * INV_LAMB);
        k[7]  = __expf((s1.w - 1.0f) * INV_LAMB);
        k[8]  = __expf((s2.x - 1.0f) * INV_LAMB);
        k[9]  = __expf((s2.y - 1.0f) * INV_LAMB);
        k[10] = __expf((s2.z - 1.0f) * INV_LAMB);
        k[11] = __expf((s2.w - 1.0f) * INV_LAMB);
        k[12] = __expf((s3.x - 1.0f) * INV_LAMB);
        k[13] = __expf((s3.y - 1.0f) * INV_LAMB);
        k[14] = __expf((s3.z - 1.0f) * INV_LAMB);
        k[15] = __expf((s3.w - 1.0f) * INV_LAMB);

        uint4 o0, o1;
        o0.x = pack_bf2(k[0], k[1]);   o0.y = pack_bf2(k[2], k[3]);
        o0.z = pack_bf2(k[4], k[5]);   o0.w = pack_bf2(k[6], k[7]);
        o1.x = pack_bf2(k[8], k[9]);   o1.y = pack_bf2(k[10], k[11]);
        o1.z = pack_bf2(k[12], k[13]); o1.w = pack_bf2(k[14], k[15]);
        uint4* op = kbase + (size_t)r * NU4;
        op[0] = o0; op[1] = o1;

        float a = 0.f, b = 0.f, c2 = 0.f, d2 = 0.f;
        #pragma unroll
        for (int i = 0; i < CPT; i += 4) {
            a += k[i]; b += k[i + 1]; c2 += k[i + 2]; d2 += k[i + 3];
        }
        float s = warp_sum((a + b) + (c2 + d2));
        if (lane == 0) red[r & 1][wid] = s;
        __syncthreads();
        float ri = 1.0f / tail_sum16(red[r & 1], lane);
        if (t == r) g_r[row0 + r] = ri;
        #pragma unroll
        for (int i = 0; i < CPT; i++) acc[i] += k[i] * ri;
    }

    float4* out = (float4*)(g_partial + (size_t)blockIdx.x * N) + t * 4;
    #pragma unroll
    for (int q = 0; q < 4; q++)
        out[q] = make_float4(acc[q * 4], acc[q * 4 + 1], acc[q * 4 + 2], acc[q * 4 + 3]);
}

// ============================================================================
// fused_pass: r_i = 1/sum_j K_ij c_j, col partials sum_i K_ij r_i, ONE read
// of K.  fp32 math; K unpacked ONCE per row into k[16] (lives across the
// barrier); c and acc in registers.  ~66 instr/row vs ~96 in the
// double-unpack variant.  Latency covered by occ 2.
// ============================================================================
__global__ __launch_bounds__(THREADS, 2) void fused_pass(void) {
    int t = threadIdx.x;
    int wid = t >> 5, lane = t & 31;
    int row0 = blockIdx.x * RPB;
    __shared__ float red[2][16];

    const uint4* __restrict__ kbase = g_K4 + (size_t)row0 * NU4 + t * 2;

    float c[CPT];
    {
        const float4* cp = (const float4*)g_c + t * 4;
        #pragma unroll
        for (int q = 0; q < 4; q++) {
            float4 v = cp[q];
            c[q * 4] = v.x; c[q * 4 + 1] = v.y; c[q * 4 + 2] = v.z; c[q * 4 + 3] = v.w;
        }
    }
    float acc[CPT];
    #pragma unroll
    for (int i = 0; i < CPT; i++) acc[i] = 0.f;

    for (int r = 0; r < RPB; r++) {
        const uint4* p = kbase + (size_t)r * NU4;
        uint4 cur0 = p[0], cur1 = p[1];
        float k[CPT];
        unpack16(cur0, cur1, k);

        float a0 = k[0] * c[0]  + k[4] * c[4]  + k[8]  * c[8]  + k[12] * c[12];
        float a1 = k[1] * c[1]  + k[5] * c[5]  + k[9]  * c[9]  + k[13] * c[13];
        float a2 = k[2] * c[2]  + k[6] * c[6]  + k[10] * c[10] + k[14] * c[14];
        float a3 = k[3] * c[3]  + k[7] * c[7]  + k[11] * c[11] + k[15] * c[15];

        float s = warp_sum((a0 + a1) + (a2 + a3));
        if (lane == 0) red[r & 1][wid] = s;
        __syncthreads();
        float ri = 1.0f / tail_sum16(red[r & 1], lane);
        if (t == r) g_r[row0 + r] = ri;
        #pragma unroll
        for (int i = 0; i < CPT; i++) acc[i] += k[i] * ri;
    }

    float4* out = (float4*)(g_partial + (size_t)blockIdx.x * N) + t * 4;
    #pragma unroll
    for (int q = 0; q < 4; q++)
        out[q] = make_float4(acc[q * 4], acc[q * 4 + 1], acc[q * 4 + 2], acc[q * 4 + 3]);
}

// ============================================================================
// Two-stage tree reduction of g_partial[512][N] -> g_c
// ============================================================================
__global__ void col_reduce1(void) {
    int jv = blockIdx.x * 256 + threadIdx.x;   // float4 col index 0..2047
    int g  = blockIdx.y;
    const float4* __restrict__ p4 = (const float4*)g_partial;
    float4 acc = make_float4(0.f, 0.f, 0.f, 0.f);
    #pragma unroll
    for (int b = 0; b < 32; b++) {
        float4 p = p4[(size_t)(g * 32 + b) * (N / 4) + jv];
        acc.x += p.x; acc.y += p.y; acc.z += p.z; acc.w += p.w;
    }
    ((float4*)g_partial2)[(size_t)g * (N / 4) + jv] = acc;
}

__global__ void col_reduce2(void) {
    int jv = blockIdx.x * 256 + threadIdx.x;
    const float4* __restrict__ p4 = (const float4*)g_partial2;
    float4 acc = make_float4(0.f, 0.f, 0.f, 0.f);
    #pragma unroll
    for (int g = 0; g < PGROUPS; g++) {
        float4 p = p4[(size_t)g * (N / 4) + jv];
        acc.x += p.x; acc.y += p.y; acc.z += p.z; acc.w += p.w;
    }
    float4 o;
    o.x = 1.0f / acc.x; o.y = 1.0f / acc.y; o.z = 1.0f / acc.z; o.w = 1.0f / acc.w;
    ((float4*)g_c)[jv] = o;
}

__global__ void diag_kernel(void) {
    int j = blockIdx.x * blockDim.x + threadIdx.x;
    const __nv_bfloat16* K = (const __nv_bfloat16*)g_K4;
    g_d[j] = __bfloat162float(K[(size_t)j * N + j]) * g_r[j] * g_c[j];
}

// ============================================================================
// loss_fused: c and dj in registers; packed depth-1 prefetch; inline unpack;
// no per-row syncs.  (fp32 math: hinge precision matters here.)
// ============================================================================
__global__ __launch_bounds__(THREADS, 2) void loss_fused(void) {
    int t = threadIdx.x;
    int wid = t >> 5, lane = t & 31;
    int row0 = blockIdx.x * RPB;
    __shared__ float rsm[RPB], dsm[RPB];
    __shared__ float red[16];

    if (t < RPB) {
        rsm[t] = g_r[row0 + t];
        dsm[t] = g_d[row0 + t];
    }

    float c[CPT], dj[CPT];
    {
        const float4* cp = (const float4*)g_c + t * 4;
        const float4* dp = (const float4*)g_d + t * 4;
        #pragma unroll
        for (int q = 0; q < 4; q++) {
            float4 v = cp[q];
            c[q * 4] = v.x; c[q * 4 + 1] = v.y; c[q * 4 + 2] = v.z; c[q * 4 + 3] = v.w;
            float4 w = dp[q];
            dj[q * 4] = w.x; dj[q * 4 + 1] = w.y; dj[q * 4 + 2] = w.z; dj[q * 4 + 3] = w.w;
        }
    }
    __syncthreads();

    const uint4* __restrict__ kbase = g_K4 + (size_t)row0 * NU4 + t * 2;
    int col0 = t * CPT;
    float l0 = 0.f, l1 = 0.f, l2 = 0.f, l3 = 0.f;

    uint4 cur0 = kbase[0], cur1 = kbase[1];

    for (int r = 0; r < RPB; r++) {
        uint4 nx0, nx1;
        if (r + 1 < RPB) {
            const uint4* p = kbase + (size_t)(r + 1) * NU4;
            nx0 = p[0]; nx1 = p[1];
        }
        float ri = rsm[r];
        float di = dsm[r];
        int row = row0 + r;

        unsigned pk[8] = {cur0.x, cur0.y, cur0.z, cur0.w, cur1.x, cur1.y, cur1.z, cur1.w};
        #pragma unroll
        for (int q = 0; q < 8; q++) {
            float2 p = unpack_bf2(pk[q]);
            int i0 = q * 2;
            float P = p.x * ri * c[i0];
            float h = fmaxf(P - dj[i0] + MARGIN, 0.f) + fmaxf(P - di + MARGIN, 0.f);
            if (col0 + i0 != row) { if (q & 1) l1 += h; else l0 += h; }
            P = p.y * ri * c[i0 + 1];
            h = fmaxf(P - dj[i0 + 1] + MARGIN, 0.f) + fmaxf(P - di + MARGIN, 0.f);
            if (col0 + i0 + 1 != row) { if (q & 1) l3 += h; else l2 += h; }
        }
        cur0 = nx0; cur1 = nx1;
    }

    float s = warp_sum((l0 + l1) + (l2 + l3));
    if (lane == 0) red[wid] = s;
    __syncthreads();
    if (wid == 0) {
        float v = (lane < 16) ? red[lane] : 0.f;
        v = warp_sum(v);
        if (lane == 0) g_block_loss[blockIdx.x] = v;
    }
}

__global__ void final_reduce_kernel(float* __restrict__ out) {
    __shared__ double sh[256];
    double acc = 0.0;
    for (int i = threadIdx.x; i < BLOCKS; i += 256) acc += (double)g_block_loss[i];
    sh[threadIdx.x] = acc;
    __syncthreads();
    #pragma unroll
    for (int s = 128; s > 0; s >>= 1) {
        if (threadIdx.x < s) sh[threadIdx.x] += sh[threadIdx.x + s];
        __syncthreads();
    }
    if (threadIdx.x == 0) out[0] = (float)sh[0];
}

extern "C" void kernel_launch(void* const* d_in, const int* in_sizes, int n_in,
                              void* d_out, int out_size) {
    const float* sims = (const float*)d_in[0];
    float* out = (float*)d_out;

    pass1_fused<<<BLOCKS, THREADS>>>(sims);
    col_reduce1<<<dim3(8, PGROUPS), 256>>>();
    col_reduce2<<<16, 256>>>();

    for (int it = 1; it < 5; it++) {
        fused_pass<<<BLOCKS, THREADS>>>();
        col_reduce1<<<dim3(8, PGROUPS), 256>>>();
        col_reduce2<<<16, 256>>>();
    }

    diag_kernel<<<32, 256>>>();
    loss_fused<<<BLOCKS, THREADS>>>();
    final_reduce_kernel<<<1, 256>>>(out);
}

// round 11
// speedup vs baseline: 1.0690x; 1.0690x over previous
#include <cuda_runtime.h>
#include <cuda_bf16.h>

#define N 8192
#define MARGIN 0.2f
#define INV_LAMB 83.333336f   // 1 / 0.012

#define BLOCKS 512
#define RPB 16                // rows per block: 512 * 16 = 8192
#define THREADS 512
#define CPT 16                // columns per thread: 512 * 16 = 8192
#define NU4 1024              // uint4 (8 bf16) per row
#define NF4 2048              // float4 per row
#define PGROUPS 16            // 512 partial rows -> 16 groups of 32

// ---- scratch (static __device__ globals; no allocations) ----
__device__ uint4  g_K4[(size_t)N * N / 8];        // K in bf16 (128 MB)
__device__ float  g_r[N];
__device__ float  g_c[N];
__device__ float  g_d[N];
__device__ float  g_partial[(size_t)BLOCKS * N];  // col partials (16 MB)
__device__ float  g_partial2[(size_t)PGROUPS * N];// stage-2 partials (512 KB)
__device__ float  g_block_loss[BLOCKS];

__device__ __forceinline__ float warp_sum(float v) {
    v += __shfl_xor_sync(0xffffffffu, v, 16);
    v += __shfl_xor_sync(0xffffffffu, v, 8);
    v += __shfl_xor_sync(0xffffffffu, v, 4);
    v += __shfl_xor_sync(0xffffffffu, v, 2);
    v += __shfl_xor_sync(0xffffffffu, v, 1);
    return v;
}

__device__ __forceinline__ float2 unpack_bf2(unsigned u) {
    float2 f;
    f.x = __uint_as_float(u << 16);
    f.y = __uint_as_float(u & 0xffff0000u);
    return f;
}

__device__ __forceinline__ unsigned pack_bf2(float lo, float hi) {
    __nv_bfloat162 h = __floats2bfloat162_rn(lo, hi);
    return *reinterpret_cast<unsigned*>(&h);
}

__device__ __forceinline__ void unpack16(const uint4& a, const uint4& b, float* k) {
    float2 p;
    p = unpack_bf2(a.x); k[0] = p.x;  k[1] = p.y;
    p = unpack_bf2(a.y); k[2] = p.x;  k[3] = p.y;
    p = unpack_bf2(a.z); k[4] = p.x;  k[5] = p.y;
    p = unpack_bf2(a.w); k[6] = p.x;  k[7] = p.y;
    p = unpack_bf2(b.x); k[8] = p.x;  k[9] = p.y;
    p = unpack_bf2(b.y); k[10] = p.x; k[11] = p.y;
    p = unpack_bf2(b.z); k[12] = p.x; k[13] = p.y;
    p = unpack_bf2(b.w); k[14] = p.x; k[15] = p.y;
}

// ============================================================================
// pass1_fused: two-sweep.
// Sweep 1: K = exp((s-1)/lamb) -> bf16 cache + per-warp row sums (no barrier).
// Then ONE barrier, finish the 16 row sums (c == 1 for iter 1).
// Sweep 2: re-read K (same-thread addresses -> L1/L2 hits), accumulate K*ri.
// ============================================================================
__global__ __launch_bounds__(THREADS, 2) void pass1_fused(const float* __restrict__ sims) {
    int t = threadIdx.x;
    int wid = t >> 5, lane = t & 31;
    int row0 = blockIdx.x * RPB;
    __shared__ float red[RPB][16];
    __shared__ float ri_sm[RPB];

    const float4* __restrict__ sbase = (const float4*)sims + (size_t)row0 * NF4 + t * 4;
    uint4* __restrict__ kbase = g_K4 + (size_t)row0 * NU4 + t * 2;

    // ---- sweep 1: exp + store K + per-warp row sums (no barriers) ----
    for (int r = 0; r < RPB; r++) {
        const float4* sp = sbase + (size_t)r * NF4;
        float4 s0 = sp[0], s1 = sp[1], s2 = sp[2], s3 = sp[3];
        float k[CPT];
        k[0]  = __expf((s0.x - 1.0f) * INV_LAMB);
        k[1]  = __expf((s0.y - 1.0f) * INV_LAMB);
        k[2]  = __expf((s0.z - 1.0f) * INV_LAMB);
        k[3]  = __expf((s0.w - 1.0f) * INV_LAMB);
        k[4]  = __expf((s1.x - 1.0f) * INV_LAMB);
        k[5]  = __expf((s1.y - 1.0f) * INV_LAMB);
        k[6]  = __expf((s1.z - 1.0f) * INV_LAMB);
        k[7]  = __expf((s1.w - 1.0f) * INV_LAMB);
        k[8]  = __expf((s2.x - 1.0f) * INV_LAMB);
        k[9]  = __expf((s2.y - 1.0f) * INV_LAMB);
        k[10] = __expf((s2.z - 1.0f) * INV_LAMB);
        k[11] = __expf((s2.w - 1.0f) * INV_LAMB);
        k[12] = __expf((s3.x - 1.0f) * INV_LAMB);
        k[13] = __expf((s3.y - 1.0f) * INV_LAMB);
        k[14] = __expf((s3.z - 1.0f) * INV_LAMB);
        k[15] = __expf((s3.w - 1.0f) * INV_LAMB);

        uint4 o0, o1;
        o0.x = pack_bf2(k[0], k[1]);   o0.y = pack_bf2(k[2], k[3]);
        o0.z = pack_bf2(k[4], k[5]);   o0.w = pack_bf2(k[6], k[7]);
        o1.x = pack_bf2(k[8], k[9]);   o1.y = pack_bf2(k[10], k[11]);
        o1.z = pack_bf2(k[12], k[13]); o1.w = pack_bf2(k[14], k[15]);
        uint4* op = kbase + (size_t)r * NU4;
        op[0] = o0; op[1] = o1;

        float a = 0.f, b = 0.f, c2 = 0.f, d2 = 0.f;
        #pragma unroll
        for (int i = 0; i < CPT; i += 4) {
            a += k[i]; b += k[i + 1]; c2 += k[i + 2]; d2 += k[i + 3];
        }
        float s = warp_sum((a + b) + (c2 + d2));
        if (lane == 0) red[r][wid] = s;
    }
    __syncthreads();
    if (t < RPB) {
        float tot = 0.f;
        #pragma unroll
        for (int w = 0; w < 16; w++) tot += red[t][w];
        float ri = 1.0f / tot;
        ri_sm[t] = ri;
        g_r[row0 + t] = ri;
    }
    __syncthreads();

    // ---- sweep 2: re-read my own K (L1/L2 hit), accumulate K*ri ----
    float acc[CPT];
    #pragma unroll
    for (int i = 0; i < CPT; i++) acc[i] = 0.f;
    for (int r = 0; r < RPB; r++) {
        const uint4* p = kbase + (size_t)r * NU4;
        uint4 a = p[0], b = p[1];
        float k[CPT];
        unpack16(a, b, k);
        float ri = ri_sm[r];
        #pragma unroll
        for (int i = 0; i < CPT; i++) acc[i] += k[i] * ri;
    }

    float4* out = (float4*)(g_partial + (size_t)blockIdx.x * N) + t * 4;
    #pragma unroll
    for (int q = 0; q < 4; q++)
        out[q] = make_float4(acc[q * 4], acc[q * 4 + 1], acc[q * 4 + 2], acc[q * 4 + 3]);
}

// ============================================================================
// fused_pass: two-sweep, 2 barriers total (vs 16).
// Sweep 1: streaming row dots (K . c) -> per-warp sums in smem, NO barriers.
// Barrier; 16 threads finish row sums -> ri_sm; barrier.
// Sweep 2: re-read rows (L2-resident: 296 CTAs x 256 KB ~ 76 MB < 126 MB L2),
// accumulate K*ri into col partials.
// ============================================================================
__global__ __launch_bounds__(THREADS, 2) void fused_pass(void) {
    int t = threadIdx.x;
    int wid = t >> 5, lane = t & 31;
    int row0 = blockIdx.x * RPB;
    __shared__ float red[RPB][16];
    __shared__ float ri_sm[RPB];

    const uint4* __restrict__ kbase = g_K4 + (size_t)row0 * NU4 + t * 2;

    float c[CPT];
    {
        const float4* cp = (const float4*)g_c + t * 4;
        #pragma unroll
        for (int q = 0; q < 4; q++) {
            float4 v = cp[q];
            c[q * 4] = v.x; c[q * 4 + 1] = v.y; c[q * 4 + 2] = v.z; c[q * 4 + 3] = v.w;
        }
    }

    // ---- sweep 1: all 16 row dots, no barriers ----
    for (int r = 0; r < RPB; r++) {
        const uint4* p = kbase + (size_t)r * NU4;
        uint4 a = p[0], b = p[1];
        float k[CPT];
        unpack16(a, b, k);
        float a0 = k[0] * c[0]  + k[4] * c[4]  + k[8]  * c[8]  + k[12] * c[12];
        float a1 = k[1] * c[1]  + k[5] * c[5]  + k[9]  * c[9]  + k[13] * c[13];
        float a2 = k[2] * c[2]  + k[6] * c[6]  + k[10] * c[10] + k[14] * c[14];
        float a3 = k[3] * c[3]  + k[7] * c[7]  + k[11] * c[11] + k[15] * c[15];
        float s = warp_sum((a0 + a1) + (a2 + a3));
        if (lane == 0) red[r][wid] = s;
    }
    __syncthreads();
    if (t < RPB) {
        float tot = 0.f;
        #pragma unroll
        for (int w = 0; w < 16; w++) tot += red[t][w];
        float ri = 1.0f / tot;
        ri_sm[t] = ri;
        g_r[row0 + t] = ri;
    }
    __syncthreads();

    // ---- sweep 2: re-read rows (L2 hits), accumulate col partials ----
    float acc[CPT];
    #pragma unroll
    for (int i = 0; i < CPT; i++) acc[i] = 0.f;
    for (int r = 0; r < RPB; r++) {
        const uint4* p = kbase + (size_t)r * NU4;
        uint4 a = p[0], b = p[1];
        float k[CPT];
        unpack16(a, b, k);
        float ri = ri_sm[r];
        #pragma unroll
        for (int i = 0; i < CPT; i++) acc[i] += k[i] * ri;
    }

    float4* out = (float4*)(g_partial + (size_t)blockIdx.x * N) + t * 4;
    #pragma unroll
    for (int q = 0; q < 4; q++)
        out[q] = make_float4(acc[q * 4], acc[q * 4 + 1], acc[q * 4 + 2], acc[q * 4 + 3]);
}

// ============================================================================
// Two-stage tree reduction of g_partial[512][N] -> g_c
// ============================================================================
__global__ void col_reduce1(void) {
    int jv = blockIdx.x * 256 + threadIdx.x;   // float4 col index 0..2047
    int g  = blockIdx.y;
    const float4* __restrict__ p4 = (const float4*)g_partial;
    float4 acc = make_float4(0.f, 0.f, 0.f, 0.f);
    #pragma unroll
    for (int b = 0; b < 32; b++) {
        float4 p = p4[(size_t)(g * 32 + b) * (N / 4) + jv];
        acc.x += p.x; acc.y += p.y; acc.z += p.z; acc.w += p.w;
    }
    ((float4*)g_partial2)[(size_t)g * (N / 4) + jv] = acc;
}

__global__ void col_reduce2(void) {
    int jv = blockIdx.x * 256 + threadIdx.x;
    const float4* __restrict__ p4 = (const float4*)g_partial2;
    float4 acc = make_float4(0.f, 0.f, 0.f, 0.f);
    #pragma unroll
    for (int g = 0; g < PGROUPS; g++) {
        float4 p = p4[(size_t)g * (N / 4) + jv];
        acc.x += p.x; acc.y += p.y; acc.z += p.z; acc.w += p.w;
    }
    float4 o;
    o.x = 1.0f / acc.x; o.y = 1.0f / acc.y; o.z = 1.0f / acc.z; o.w = 1.0f / acc.w;
    ((float4*)g_c)[jv] = o;
}

__global__ void diag_kernel(void) {
    int j = blockIdx.x * blockDim.x + threadIdx.x;
    const __nv_bfloat16* K = (const __nv_bfloat16*)g_K4;
    g_d[j] = __bfloat162float(K[(size_t)j * N + j]) * g_r[j] * g_c[j];
}

// ============================================================================
// loss_fused: c and dj in registers; packed depth-1 prefetch; inline unpack;
// no per-row syncs.  (fp32 math: hinge precision matters here.)
// ============================================================================
__global__ __launch_bounds__(THREADS, 2) void loss_fused(void) {
    int t = threadIdx.x;
    int wid = t >> 5, lane = t & 31;
    int row0 = blockIdx.x * RPB;
    __shared__ float rsm[RPB], dsm[RPB];
    __shared__ float red[16];

    if (t < RPB) {
        rsm[t] = g_r[row0 + t];
        dsm[t] = g_d[row0 + t];
    }

    float c[CPT], dj[CPT];
    {
        const float4* cp = (const float4*)g_c + t * 4;
        const float4* dp = (const float4*)g_d + t * 4;
        #pragma unroll
        for (int q = 0; q < 4; q++) {
            float4 v = cp[q];
            c[q * 4] = v.x; c[q * 4 + 1] = v.y; c[q * 4 + 2] = v.z; c[q * 4 + 3] = v.w;
            float4 w = dp[q];
            dj[q * 4] = w.x; dj[q * 4 + 1] = w.y; dj[q * 4 + 2] = w.z; dj[q * 4 + 3] = w.w;
        }
    }
    __syncthreads();

    const uint4* __restrict__ kbase = g_K4 + (size_t)row0 * NU4 + t * 2;
    int col0 = t * CPT;
    float l0 = 0.f, l1 = 0.f, l2 = 0.f, l3 = 0.f;

    uint4 cur0 = kbase[0], cur1 = kbase[1];

    for (int r = 0; r < RPB; r++) {
        uint4 nx0, nx1;
        if (r + 1 < RPB) {
            const uint4* p = kbase + (size_t)(r + 1) * NU4;
            nx0 = p[0]; nx1 = p[1];
        }
        float ri = rsm[r];
        float di = dsm[r];
        int row = row0 + r;

        unsigned pk[8] = {cur0.x, cur0.y, cur0.z, cur0.w, cur1.x, cur1.y, cur1.z, cur1.w};
        #pragma unroll
        for (int q = 0; q < 8; q++) {
            float2 p = unpack_bf2(pk[q]);
            int i0 = q * 2;
            float P = p.x * ri * c[i0];
            float h = fmaxf(P - dj[i0] + MARGIN, 0.f) + fmaxf(P - di + MARGIN, 0.f);
            if (col0 + i0 != row) { if (q & 1) l1 += h; else l0 += h; }
            P = p.y * ri * c[i0 + 1];
            h = fmaxf(P - dj[i0 + 1] + MARGIN, 0.f) + fmaxf(P - di + MARGIN, 0.f);
            if (col0 + i0 + 1 != row) { if (q & 1) l3 += h; else l2 += h; }
        }
        cur0 = nx0; cur1 = nx1;
    }

    float s = warp_sum((l0 + l1) + (l2 + l3));
    if (lane == 0) red[wid] = s;
    __syncthreads();
    if (wid == 0) {
        float v = (lane < 16) ? red[lane] : 0.f;
        v = warp_sum(v);
        if (lane == 0) g_block_loss[blockIdx.x] = v;
    }
}

__global__ void final_reduce_kernel(float* __restrict__ out) {
    __shared__ double sh[256];
    double acc = 0.0;
    for (int i = threadIdx.x; i < BLOCKS; i += 256) acc += (double)g_block_loss[i];
    sh[threadIdx.x] = acc;
    __syncthreads();
    #pragma unroll
    for (int s = 128; s > 0; s >>= 1) {
        if (threadIdx.x < s) sh[threadIdx.x] += sh[threadIdx.x + s];
        __syncthreads();
    }
    if (threadIdx.x == 0) out[0] = (float)sh[0];
}

extern "C" void kernel_launch(void* const* d_in, const int* in_sizes, int n_in,
                              void* d_out, int out_size) {
    const float* sims = (const float*)d_in[0];
    float* out = (float*)d_out;

    pass1_fused<<<BLOCKS, THREADS>>>(sims);
    col_reduce1<<<dim3(8, PGROUPS), 256>>>();
    col_reduce2<<<16, 256>>>();

    for (int it = 1; it < 5; it++) {
        fused_pass<<<BLOCKS, THREADS>>>();
        col_reduce1<<<dim3(8, PGROUPS), 256>>>();
        col_reduce2<<<16, 256>>>();
    }

    diag_kernel<<<32, 256>>>();
    loss_fused<<<BLOCKS, THREADS>>>();
    final_reduce_kernel<<<1, 256>>>(out);
}